// round 12
// baseline (speedup 1.0000x reference)
#include <cuda_runtime.h>
#include <cuda_bf16.h>
#include <cstdint>
#include <cstddef>

// ---------------- problem constants ----------------
#define B_TOTAL 32768
#define T_STEPS 30
#define HDIM    384
#define BT      64          // batch rows per CTA
#define NTH     512         // 16 warps = 2 groups of 8
#define KTOT    512         // [x(128) | hidden(384)]
#define NCOLS   1536        // 384 h * 4 gates (r,z,s,hn), gate-interleaved
#define NCHUNK  12          // 128 cols per chunk
#define SLAB_U32 4096       // one slab = 2 ksteps(32 k) x 128 cols, hi+lo fused
#define MAIN_SLABS 192      // 12 chunks * 16 slabs
#define DEC_SLABS  12
#define DSLAB_U32  2048
#define D1      64
#define D1PAD   65
#define A_U32   32768       // 32 ksteps * 1024 u32 (frag-ordered, hi+lo)
#define CHUNK_U32 65536     // 16 slabs * 4096 u32 per 128-col chunk

// ---------------- device scratch (no allocations allowed) ----------------
__device__ uint32_t g_Wf[(size_t)MAIN_SLABS * SLAB_U32];   // 3 MB main-W frags
__device__ uint32_t g_Wd1f[DEC_SLABS * DSLAB_U32];         // 96 KB Wd1 frags
__device__ float    g_bias[NCOLS];
__device__ float    g_hidden[(size_t)B_TOTAL * HDIM];      // fp32 recurrent state

// ---------------- helpers ----------------
__device__ __forceinline__ float sigmoid_f(float x) { return 1.0f / (1.0f + __expf(-x)); }
__device__ __forceinline__ float tanh_f(float x) {
    float e2 = __expf(2.0f * x);
    return 1.0f - 2.0f / (e2 + 1.0f);
}
__device__ __forceinline__ float elu_f(float x) {
    return x > 0.0f ? x : (__expf(x) - 1.0f);
}
__device__ __forceinline__ void prefetch_l1(const void* p) {
    asm volatile("prefetch.global.L1 [%0];" :: "l"(p));
}
__device__ __forceinline__ void mma16816(float* c,
    uint32_t a0, uint32_t a1, uint32_t a2, uint32_t a3, uint32_t b0, uint32_t b1)
{
    asm volatile(
        "mma.sync.aligned.m16n8k16.row.col.f32.bf16.bf16.f32 "
        "{%0,%1,%2,%3}, {%4,%5,%6,%7}, {%8,%9}, {%0,%1,%2,%3};\n"
        : "+f"(c[0]), "+f"(c[1]), "+f"(c[2]), "+f"(c[3])
        : "r"(a0), "r"(a1), "r"(a2), "r"(a3), "r"(b0), "r"(b1));
}

// Write element pair (row, k even, k+1) into frag-ordered A smem (hi + lo).
// A layout (u32): kstep*1024 + mt*256 + [hi:0 | lo:128] + lane*4 + reg
__device__ __forceinline__ void a_write_pair(uint32_t* A, int row, int k,
                                             float v0, float v1)
{
    int kstep = k >> 4, kk = k & 15;
    int mt = row >> 4, r16 = row & 15;
    int gid = r16 & 7, hi8 = r16 >> 3;
    int tg2 = (kk & 7) >> 1, k8 = kk >> 3;
    int reg = hi8 + 2 * k8;
    int lane = gid * 4 + tg2;
    uint32_t uidx = kstep * 1024 + mt * 256 + lane * 4 + reg;
    __nv_bfloat16 h0 = __float2bfloat16(v0);
    __nv_bfloat16 h1 = __float2bfloat16(v1);
    unsigned hw = (unsigned)__bfloat16_as_ushort(h0)
                | ((unsigned)__bfloat16_as_ushort(h1) << 16);
    unsigned lw = (unsigned)__bfloat16_as_ushort(__float2bfloat16(v0 - __bfloat162float(h0)))
                | ((unsigned)__bfloat16_as_ushort(__float2bfloat16(v1 - __bfloat162float(h1))) << 16);
    A[uidx]       = hw;
    A[uidx + 128] = lw;
}

// ----------------------------------------------------------------------------
// Pack: W = [W_ih | W_hh] -> bf16 hi/lo, fused-fragment order (unchanged).
// ----------------------------------------------------------------------------
__global__ void pack_kernel(const float* __restrict__ W_ih,
                            const float* __restrict__ W_hh,
                            const float* __restrict__ b_ih,
                            const float* __restrict__ b_hh,
                            const float* __restrict__ Wd1)
{
    int idx = blockIdx.x * blockDim.x + threadIdx.x;
    __nv_bfloat16* Wf16   = (__nv_bfloat16*)g_Wf;
    __nv_bfloat16* Wd1f16 = (__nv_bfloat16*)g_Wd1f;

    if (idx < KTOT * NCOLS) {
        int k = idx / NCOLS;
        int col = idx - k * NCOLS;
        int chunk = col >> 7, q = col & 127;
        int i = q >> 2, g = q & 3, h = chunk * 32 + i;
        float v;
        if (g < 3) {
            int row = g * HDIM + h;
            v = (k < 128) ? W_ih[row * 128 + k] : W_hh[row * HDIM + (k - 128)];
        } else {
            v = (k < 128) ? 0.0f : W_hh[(2 * HDIM + h) * HDIM + (k - 128)];
        }
        __nv_bfloat16 hi = __float2bfloat16(v);
        __nv_bfloat16 lo = __float2bfloat16(v - __bfloat162float(hi));
        int kstep = k >> 4, kk = k & 15;
        int reg = kk >> 3, tg2 = (kk & 7) >> 1, half = kk & 1;
        int ntg = q >> 3, n = q & 7;
        int lane = n * 4 + tg2;
        size_t base = (size_t)(chunk * 32 + kstep) * 2048;
        size_t uhi = base + ntg * 128 + lane * 4 + reg;
        Wf16[uhi * 2 + half]       = hi;
        Wf16[(uhi + 2) * 2 + half] = lo;
    }
    if (idx < HDIM * D1) {
        int k = idx >> 6, j = idx & 63;
        float v = Wd1[j * HDIM + k];
        __nv_bfloat16 hi = __float2bfloat16(v);
        __nv_bfloat16 lo = __float2bfloat16(v - __bfloat162float(hi));
        int kstep = k >> 4, kk = k & 15;
        int reg = kk >> 3, tg2 = (kk & 7) >> 1, half = kk & 1;
        int ntg = j >> 3, n = j & 7;
        int lane = n * 4 + tg2;
        size_t uhi = (size_t)kstep * 1024 + ntg * 128 + lane * 4 + reg;
        Wd1f16[uhi * 2 + half]       = hi;
        Wd1f16[(uhi + 2) * 2 + half] = lo;
    }
    if (idx < NCOLS) {
        int c = idx >> 7, q = idx & 127, i = q >> 2, g = q & 3;
        int h = c * 32 + i;
        float bv;
        if (g == 3) bv = b_hh[2 * HDIM + h];
        else        bv = b_ih[g * HDIM + h] + b_hh[g * HDIM + h];
        g_bias[idx] = bv;
    }
}

// ----------------------------------------------------------------------------
// Persistent per-tile decoder. B operands stream from L2 via LDG.128 in
// fragment order; mw==0 warps prefetch 2 ksteps ahead into L1 so the paired
// mw warps' LDGs are L1 hits (dedup: L2 sees each line once). No mainloop
// barriers. 2 groups of 8 warps on 2 chunks; mw = gwarp&1, nw = gwarp>>1.
// ----------------------------------------------------------------------------
__global__ void __launch_bounds__(NTH, 1)
decoder_kernel(const float* __restrict__ init_hidden,
               const float* __restrict__ plan,
               const float* __restrict__ gate,
               const float* __restrict__ init_state,
               const float* __restrict__ Wp, const float* __restrict__ bp,
               const float* __restrict__ Ws, const float* __restrict__ bs,
               const float* __restrict__ Wd2, const float* __restrict__ bd2,
               const float* __restrict__ bd1,
               float* __restrict__ out)
{
    extern __shared__ uint32_t sm32[];
    uint32_t* A_f  = sm32;                         // 32768 u32 (128KB)
    float* d1s    = (float*)(A_f + A_U32);         // 64*65 = 4160
    float* bias_s = d1s + BT * D1PAD;              // 1536
    float* xcoef  = bias_s + NCOLS;                // 1024
    float* bd1_s  = xcoef + 1024;                  // 64
    float* wd2_s  = bd1_s + D1;                    // 192
    float* bd2_s  = wd2_s + 192;                   // 4
    float* plan_s = bd2_s + 4;                     // 192
    float* st_s   = plan_s + BT * 3;               // 192
    float* gate_s = st_s + BT * 3;                 // 64
    float* red    = (float*)A_f;                   // decode reduction: x-kstep area (dead)

    const int tid   = threadIdx.x;
    const int lane  = tid & 31;
    const int warp  = tid >> 5;
    const int group = warp >> 3;     // 0 or 1
    const int gwarp = warp & 7;      // warp within group
    const int gid   = lane >> 2;     // 0..7
    const int tg    = lane & 3;      // 0..3
    const int mw    = gwarp & 1;     // 32-row half
    const int nw    = gwarp >> 1;    // 32-col quarter of 128-chunk
    const int bg0   = blockIdx.x * BT;
    const uint32_t woff  = (uint32_t)(nw * 512 + lane * 4);   // main B warp offset
    const uint32_t dwoff = (uint32_t)(nw * 256 + lane * 4);   // decode B warp offset

    // ---- stage constants ----
    for (int i = tid; i < NCOLS; i += NTH) bias_s[i] = g_bias[i];
    if (tid < 128) {
        xcoef[tid * 8 + 0] = Ws[tid * 3 + 0];
        xcoef[tid * 8 + 1] = Ws[tid * 3 + 1];
        xcoef[tid * 8 + 2] = Ws[tid * 3 + 2];
        xcoef[tid * 8 + 3] = bs[tid];
        xcoef[tid * 8 + 4] = Wp[tid * 3 + 0];
        xcoef[tid * 8 + 5] = Wp[tid * 3 + 1];
        xcoef[tid * 8 + 6] = Wp[tid * 3 + 2];
        xcoef[tid * 8 + 7] = bp[tid];
    }
    if (tid < D1)  bd1_s[tid] = bd1[tid];
    if (tid < 192) wd2_s[tid] = Wd2[tid];
    if (tid < 3)   bd2_s[tid] = bd2[tid];
    if (tid < BT * 3) st_s[tid] = init_state[bg0 * 3 + tid];
    if (tid < BT)     gate_s[tid] = gate[bg0 + tid];

    // ---- init hidden: fp32 -> g_hidden and frag hi/lo -> A smem ----
    {
        const float4* src = (const float4*)(init_hidden + (size_t)bg0 * HDIM);
        float4* gh = (float4*)(g_hidden + (size_t)bg0 * HDIM);
        for (int i = tid; i < BT * HDIM / 4; i += NTH) {
            float4 v = src[i];
            gh[i] = v;
            int r = i / (HDIM / 4);
            int h4 = (i - r * (HDIM / 4)) * 4;
            a_write_pair(A_f, r, 128 + h4,     v.x, v.y);
            a_write_pair(A_f, r, 128 + h4 + 2, v.z, v.w);
        }
    }
    __syncthreads();

    // x-producer mapping: 512 threads -> (row b, 16-col group)
    const int xb  = tid & 63;
    const int xcg = (tid >> 6) * 16;

    for (int t = 0; t < T_STEPS; ++t) {
        // ---- stage plan_t ----
        if (tid < BT * 3) {
            int b = tid / 3, j = tid - b * 3;
            plan_s[tid] = plan[(size_t)(bg0 + b) * (T_STEPS * 3) + t * 3 + j];
        }
        __syncthreads();

        // ---- x = state@Ws^T + bs + gate*(plan@Wp^T + bp), frag hi/lo ----
        {
            float s0 = st_s[xb * 3], s1 = st_s[xb * 3 + 1], s2 = st_s[xb * 3 + 2];
            float p0 = plan_s[xb * 3], p1 = plan_s[xb * 3 + 1], p2 = plan_s[xb * 3 + 2];
            float gt = gate_s[xb];
            #pragma unroll 4
            for (int jj = 0; jj < 16; jj += 2) {
                const float* c0 = xcoef + (xcg + jj) * 8;
                const float* c1 = c0 + 8;
                float v0 = fmaf(c0[0], s0, fmaf(c0[1], s1, fmaf(c0[2], s2, c0[3])))
                         + gt * fmaf(c0[4], p0, fmaf(c0[5], p1, fmaf(c0[6], p2, c0[7])));
                float v1 = fmaf(c1[0], s0, fmaf(c1[1], s1, fmaf(c1[2], s2, c1[3])))
                         + gt * fmaf(c1[4], p0, fmaf(c1[5], p1, fmaf(c1[6], p2, c1[7])));
                a_write_pair(A_f, xb, xcg + jj, v0, v1);
            }
        }
        __syncthreads();

        // ======= main GEMM: 2 groups, group g owns chunks 2*cp+g; B via LDG =======
        uint4 bn[4];   // prefetched B for next kstep (registers)
        {
            const uint32_t* p = g_Wf + (size_t)group * CHUNK_U32 + woff;
            #pragma unroll
            for (int nt = 0; nt < 4; ++nt)
                bn[nt] = __ldg((const uint4*)(p + nt * 128));
            if (mw == 0) {   // L1 prefetch for kstep 1
                const uint32_t* q = p + 2048;
                #pragma unroll
                for (int nt = 0; nt < 4; ++nt)
                    prefetch_l1(q + nt * 128);
            }
        }

        for (int cp = 0; cp < 6; ++cp) {
            const int c = 2 * cp + group;
            float acc[2][4][4];
            #pragma unroll
            for (int mt = 0; mt < 2; ++mt)
            #pragma unroll
            for (int nt = 0; nt < 4; ++nt) {
                int col = c * 128 + nw * 32 + nt * 8 + 2 * tg;
                float b0v = bias_s[col], b1v = bias_s[col + 1];
                acc[mt][nt][0] = b0v; acc[mt][nt][1] = b1v;
                acc[mt][nt][2] = b0v; acc[mt][nt][3] = b1v;
            }
            // prefetch oldh for this chunk's epilogue
            float oldv[2][4][2];
            if ((tg & 1) == 0) {
                #pragma unroll
                for (int mt = 0; mt < 2; ++mt)
                #pragma unroll
                for (int nt = 0; nt < 4; ++nt) {
                    int h = c * 32 + nw * 8 + nt * 2 + (tg >> 1);
                    size_t gr = (size_t)(bg0 + mw * 32 + mt * 16 + gid) * HDIM + h;
                    oldv[mt][nt][0] = g_hidden[gr];
                    oldv[mt][nt][1] = g_hidden[gr + (size_t)8 * HDIM];
                }
            }

            for (int kstep = 0; kstep < 32; ++kstep) {
                uint4 bc[4] = {bn[0], bn[1], bn[2], bn[3]};
                // L1 prefetch for kstep+2 (mw==0 warps only -> dedup at L2)
                if (mw == 0) {
                    int pk = kstep + 2;
                    size_t paddr;
                    bool valid = true;
                    if (pk < 32)      paddr = (size_t)c * CHUNK_U32 + (size_t)pk * 2048;
                    else if (cp < 5)  paddr = (size_t)(c + 2) * CHUNK_U32 + (size_t)(pk - 32) * 2048;
                    else              valid = false;
                    if (valid) {
                        const uint32_t* q = g_Wf + paddr + woff;
                        #pragma unroll
                        for (int nt = 0; nt < 4; ++nt)
                            prefetch_l1(q + nt * 128);
                    }
                }
                // register prefetch for kstep+1 (should hit L1)
                if (kstep < 31 || cp < 5) {
                    size_t naddr = (kstep < 31)
                        ? (size_t)c * CHUNK_U32 + (size_t)(kstep + 1) * 2048
                        : (size_t)(c + 2) * CHUNK_U32;
                    const uint32_t* p = g_Wf + naddr + woff;
                    #pragma unroll
                    for (int nt = 0; nt < 4; ++nt)
                        bn[nt] = __ldg((const uint4*)(p + nt * 128));
                }
                uint4 ah[2], al[2];
                #pragma unroll
                for (int mt = 0; mt < 2; ++mt) {
                    const uint32_t* ab = A_f + kstep * 1024 + (mw * 2 + mt) * 256 + lane * 4;
                    ah[mt] = *(const uint4*)ab;
                    al[mt] = *(const uint4*)(ab + 128);
                }
                // term-major: hh, hl, lh — no back-to-back RAW on any acc
                #pragma unroll
                for (int mt = 0; mt < 2; ++mt)
                #pragma unroll
                for (int nt = 0; nt < 4; ++nt)
                    mma16816(acc[mt][nt], ah[mt].x, ah[mt].y, ah[mt].z, ah[mt].w,
                             bc[nt].x, bc[nt].y);
                #pragma unroll
                for (int mt = 0; mt < 2; ++mt)
                #pragma unroll
                for (int nt = 0; nt < 4; ++nt)
                    mma16816(acc[mt][nt], ah[mt].x, ah[mt].y, ah[mt].z, ah[mt].w,
                             bc[nt].z, bc[nt].w);
                #pragma unroll
                for (int mt = 0; mt < 2; ++mt)
                #pragma unroll
                for (int nt = 0; nt < 4; ++nt)
                    mma16816(acc[mt][nt], al[mt].x, al[mt].y, al[mt].z, al[mt].w,
                             bc[nt].x, bc[nt].y);
            }

            // ---- GRU pointwise (group-local; h ranges disjoint across groups) ----
            #pragma unroll
            for (int mt = 0; mt < 2; ++mt)
            #pragma unroll
            for (int nt = 0; nt < 4; ++nt) {
                float p0 = __shfl_xor_sync(0xffffffffu, acc[mt][nt][0], 1);
                float p1 = __shfl_xor_sync(0xffffffffu, acc[mt][nt][1], 1);
                float p2 = __shfl_xor_sync(0xffffffffu, acc[mt][nt][2], 1);
                float p3 = __shfl_xor_sync(0xffffffffu, acc[mt][nt][3], 1);
                if ((tg & 1) == 0) {
                    int h = c * 32 + nw * 8 + nt * 2 + (tg >> 1);
                    size_t gr = (size_t)(bg0 + mw * 32 + mt * 16 + gid) * HDIM + h;
                    float rg = sigmoid_f(acc[mt][nt][0]);
                    float zg = sigmoid_f(acc[mt][nt][1]);
                    float ng = tanh_f(p0 + (rg - 1.0f) * p1);   // s + (r-1)*hn
                    g_hidden[gr] = (1.0f - zg) * ng + zg * oldv[mt][nt][0];
                    float rg2 = sigmoid_f(acc[mt][nt][2]);
                    float zg2 = sigmoid_f(acc[mt][nt][3]);
                    float ng2 = tanh_f(p2 + (rg2 - 1.0f) * p3);
                    g_hidden[gr + (size_t)8 * HDIM] =
                        (1.0f - zg2) * ng2 + zg2 * oldv[mt][nt][1];
                }
            }
        }
        __syncthreads();   // all pointwise g_hidden writes done (both groups)

        // ---- refresh A smem hidden frags (hi/lo) from fp32 g_hidden ----
        {
            const float4* gh = (const float4*)(g_hidden + (size_t)bg0 * HDIM);
            for (int i = tid; i < BT * HDIM / 4; i += NTH) {
                float4 v = gh[i];
                int r = i / (HDIM / 4);
                int h4 = (i - r * (HDIM / 4)) * 4;
                a_write_pair(A_f, r, 128 + h4,     v.x, v.y);
                a_write_pair(A_f, r, 128 + h4 + 2, v.z, v.w);
            }
        }
        __syncthreads();

        // ======= decode GEMM: K split across groups; B via LDG + L1 prefetch =======
        float accd[2][2][4];
        {
            uint4 dbn[2];
            {
                const uint32_t* p = g_Wd1f + (size_t)(group * 12) * 1024 + dwoff;
                #pragma unroll
                for (int nt = 0; nt < 2; ++nt)
                    dbn[nt] = __ldg((const uint4*)(p + nt * 128));
                if (mw == 0) {
                    const uint32_t* q = p + 1024;
                    #pragma unroll
                    for (int nt = 0; nt < 2; ++nt)
                        prefetch_l1(q + nt * 128);
                }
            }
            #pragma unroll
            for (int mt = 0; mt < 2; ++mt)
            #pragma unroll
            for (int nt = 0; nt < 2; ++nt) {
                float b0v = 0.0f, b1v = 0.0f;
                if (group == 0) {
                    int col = nw * 16 + nt * 8 + 2 * tg;
                    b0v = bd1_s[col]; b1v = bd1_s[col + 1];
                }
                accd[mt][nt][0] = b0v; accd[mt][nt][1] = b1v;
                accd[mt][nt][2] = b0v; accd[mt][nt][3] = b1v;
            }
            for (int d = 0; d < 12; ++d) {
                uint4 dbc[2] = {dbn[0], dbn[1]};
                if (mw == 0 && d + 2 < 12) {
                    const uint32_t* q = g_Wd1f + (size_t)(group * 12 + d + 2) * 1024 + dwoff;
                    #pragma unroll
                    for (int nt = 0; nt < 2; ++nt)
                        prefetch_l1(q + nt * 128);
                }
                if (d < 11) {
                    const uint32_t* p = g_Wd1f + (size_t)(group * 12 + d + 1) * 1024 + dwoff;
                    #pragma unroll
                    for (int nt = 0; nt < 2; ++nt)
                        dbn[nt] = __ldg((const uint4*)(p + nt * 128));
                }
                int kstep = 8 + group * 12 + d;   // hidden region of A
                uint4 ah[2], al[2];
                #pragma unroll
                for (int mt = 0; mt < 2; ++mt) {
                    const uint32_t* ab = A_f + kstep * 1024 + (mw * 2 + mt) * 256 + lane * 4;
                    ah[mt] = *(const uint4*)ab;
                    al[mt] = *(const uint4*)(ab + 128);
                }
                #pragma unroll
                for (int mt = 0; mt < 2; ++mt)
                #pragma unroll
                for (int nt = 0; nt < 2; ++nt)
                    mma16816(accd[mt][nt], ah[mt].x, ah[mt].y, ah[mt].z, ah[mt].w,
                             dbc[nt].x, dbc[nt].y);
                #pragma unroll
                for (int mt = 0; mt < 2; ++mt)
                #pragma unroll
                for (int nt = 0; nt < 2; ++nt)
                    mma16816(accd[mt][nt], ah[mt].x, ah[mt].y, ah[mt].z, ah[mt].w,
                             dbc[nt].z, dbc[nt].w);
                #pragma unroll
                for (int mt = 0; mt < 2; ++mt)
                #pragma unroll
                for (int nt = 0; nt < 2; ++nt)
                    mma16816(accd[mt][nt], al[mt].x, al[mt].y, al[mt].z, al[mt].w,
                             dbc[nt].x, dbc[nt].y);
            }
        }
        __syncthreads();   // both groups done: A x-region (red) now dead, safe to write

        if (group == 1) {  // stage partial sums
            int base = (gwarp * 32 + lane) * 16;
            #pragma unroll
            for (int mt = 0; mt < 2; ++mt)
            #pragma unroll
            for (int nt = 0; nt < 2; ++nt) {
                int o = base + (mt * 2 + nt) * 4;
                red[o]     = accd[mt][nt][0];
                red[o + 1] = accd[mt][nt][1];
                red[o + 2] = accd[mt][nt][2];
                red[o + 3] = accd[mt][nt][3];
            }
        }
        __syncthreads();

        if (group == 0) {  // reduce + ELU -> d1s
            int base = (gwarp * 32 + lane) * 16;
            #pragma unroll
            for (int mt = 0; mt < 2; ++mt)
            #pragma unroll
            for (int nt = 0; nt < 2; ++nt) {
                int o = base + (mt * 2 + nt) * 4;
                float v0 = accd[mt][nt][0] + red[o];
                float v1 = accd[mt][nt][1] + red[o + 1];
                float v2 = accd[mt][nt][2] + red[o + 2];
                float v3 = accd[mt][nt][3] + red[o + 3];
                int col = nw * 16 + nt * 8 + 2 * tg;
                int row = mw * 32 + mt * 16 + gid;
                d1s[row * D1PAD + col]           = elu_f(v0);
                d1s[row * D1PAD + col + 1]       = elu_f(v1);
                d1s[(row + 8) * D1PAD + col]     = elu_f(v2);
                d1s[(row + 8) * D1PAD + col + 1] = elu_f(v3);
            }
        }
        __syncthreads();

        // ---- decode layer 2 + state update + output ----
        if (tid < BT * 3) {
            int b = tid / 3, j = tid - b * 3;
            const float* w = wd2_s + j * 64;
            const float* d = d1s + b * D1PAD;
            float sum = bd2_s[j];
            #pragma unroll
            for (int k = 0; k < 64; ++k)
                sum = fmaf(d[k], w[k], sum);
            float ns = st_s[tid] + sum;
            st_s[tid] = ns;
            out[(size_t)(bg0 + b) * (T_STEPS * 3) + t * 3 + j] = ns;
        }
        __syncthreads();
    }
}

// ----------------------------------------------------------------------------
extern "C" void kernel_launch(void* const* d_in, const int* in_sizes, int n_in,
                              void* d_out, int out_size)
{
    (void)in_sizes; (void)n_in; (void)out_size;
    const float* init_hidden = (const float*)d_in[0];
    const float* plan        = (const float*)d_in[1];
    const float* gate        = (const float*)d_in[2];
    const float* init_state  = (const float*)d_in[3];
    const float* Wp   = (const float*)d_in[4];
    const float* bp   = (const float*)d_in[5];
    const float* Ws   = (const float*)d_in[6];
    const float* bs   = (const float*)d_in[7];
    const float* W_ih = (const float*)d_in[8];
    const float* b_ih = (const float*)d_in[9];
    const float* W_hh = (const float*)d_in[10];
    const float* b_hh = (const float*)d_in[11];
    const float* Wd1  = (const float*)d_in[12];
    const float* bd1  = (const float*)d_in[13];
    const float* Wd2  = (const float*)d_in[14];
    const float* bd2  = (const float*)d_in[15];
    float* out = (float*)d_out;

    pack_kernel<<<(KTOT * NCOLS + 255) / 256, 256>>>(W_ih, W_hh, b_ih, b_hh, Wd1);

    const int smem_bytes = (A_U32 + BT * D1PAD + NCOLS + 1024
                            + D1 + 192 + 4 + BT * 3 + BT * 3 + BT) * 4;
    cudaFuncSetAttribute(decoder_kernel,
                         cudaFuncAttributeMaxDynamicSharedMemorySize, smem_bytes);
    decoder_kernel<<<B_TOTAL / BT, NTH, smem_bytes>>>(
        init_hidden, plan, gate, init_state,
        Wp, bp, Ws, bs, Wd2, bd2, bd1, out);
}

// round 13
// speedup vs baseline: 1.0579x; 1.0579x over previous
#include <cuda_runtime.h>
#include <cuda_bf16.h>
#include <cstdint>
#include <cstddef>

// ---------------- problem constants ----------------
#define B_TOTAL 32768
#define T_STEPS 30
#define HDIM    384
#define BT      64          // batch rows per CTA
#define NTH     512         // 16 warps = 2 groups of 8
#define KTOT    512         // [x(128) | hidden(384)]
#define NCOLS   1536        // 384 h * 4 gates (r,z,s,hn), gate-interleaved
#define NCHUNK  12          // 128 cols per chunk
#define SLAB_U32 4096       // one slab = 2 ksteps(32 k) x 128 cols, hi+lo fused
#define MAIN_SLABS 192      // 12 chunks * 16 slabs
#define DEC_SLABS  12
#define DSLAB_U32  2048
#define D1      64
#define D1PAD   65
#define A_U32   32768       // 32 ksteps * 1024 u32 (frag-ordered, hi+lo)
#define CHUNK_U32 65536     // 16 slabs * 4096 u32 per 128-col chunk

// ---------------- device scratch (no allocations allowed) ----------------
__device__ uint32_t g_Wf[(size_t)MAIN_SLABS * SLAB_U32];   // 3 MB main-W frags
__device__ uint32_t g_Wd1f[DEC_SLABS * DSLAB_U32];         // 96 KB Wd1 frags
__device__ float    g_bias[NCOLS];
__device__ float    g_hidden[(size_t)B_TOTAL * HDIM];      // fp32 recurrent state

// ---------------- helpers ----------------
__device__ __forceinline__ float sigmoid_f(float x) { return 1.0f / (1.0f + __expf(-x)); }
__device__ __forceinline__ float tanh_f(float x) {
    float e2 = __expf(2.0f * x);
    return 1.0f - 2.0f / (e2 + 1.0f);
}
__device__ __forceinline__ float elu_f(float x) {
    return x > 0.0f ? x : (__expf(x) - 1.0f);
}
__device__ __forceinline__ void mma16816(float* c,
    uint32_t a0, uint32_t a1, uint32_t a2, uint32_t a3, uint32_t b0, uint32_t b1)
{
    asm volatile(
        "mma.sync.aligned.m16n8k16.row.col.f32.bf16.bf16.f32 "
        "{%0,%1,%2,%3}, {%4,%5,%6,%7}, {%8,%9}, {%0,%1,%2,%3};\n"
        : "+f"(c[0]), "+f"(c[1]), "+f"(c[2]), "+f"(c[3])
        : "r"(a0), "r"(a1), "r"(a2), "r"(a3), "r"(b0), "r"(b1));
}

// Write element pair (row, k even, k+1) into frag-ordered A smem (hi + lo).
// A layout (u32): kstep*1024 + mt*256 + [hi:0 | lo:128] + lane*4 + reg
__device__ __forceinline__ void a_write_pair(uint32_t* A, int row, int k,
                                             float v0, float v1)
{
    int kstep = k >> 4, kk = k & 15;
    int mt = row >> 4, r16 = row & 15;
    int gid = r16 & 7, hi8 = r16 >> 3;
    int tg2 = (kk & 7) >> 1, k8 = kk >> 3;
    int reg = hi8 + 2 * k8;
    int lane = gid * 4 + tg2;
    uint32_t uidx = kstep * 1024 + mt * 256 + lane * 4 + reg;
    __nv_bfloat16 h0 = __float2bfloat16(v0);
    __nv_bfloat16 h1 = __float2bfloat16(v1);
    unsigned hw = (unsigned)__bfloat16_as_ushort(h0)
                | ((unsigned)__bfloat16_as_ushort(h1) << 16);
    unsigned lw = (unsigned)__bfloat16_as_ushort(__float2bfloat16(v0 - __bfloat162float(h0)))
                | ((unsigned)__bfloat16_as_ushort(__float2bfloat16(v1 - __bfloat162float(h1))) << 16);
    A[uidx]       = hw;
    A[uidx + 128] = lw;
}

// ----------------------------------------------------------------------------
// Pack: W = [W_ih | W_hh] -> bf16 hi/lo, fused-fragment order (unchanged).
// ----------------------------------------------------------------------------
__global__ void pack_kernel(const float* __restrict__ W_ih,
                            const float* __restrict__ W_hh,
                            const float* __restrict__ b_ih,
                            const float* __restrict__ b_hh,
                            const float* __restrict__ Wd1)
{
    int idx = blockIdx.x * blockDim.x + threadIdx.x;
    __nv_bfloat16* Wf16   = (__nv_bfloat16*)g_Wf;
    __nv_bfloat16* Wd1f16 = (__nv_bfloat16*)g_Wd1f;

    if (idx < KTOT * NCOLS) {
        int k = idx / NCOLS;
        int col = idx - k * NCOLS;
        int chunk = col >> 7, q = col & 127;
        int i = q >> 2, g = q & 3, h = chunk * 32 + i;
        float v;
        if (g < 3) {
            int row = g * HDIM + h;
            v = (k < 128) ? W_ih[row * 128 + k] : W_hh[row * HDIM + (k - 128)];
        } else {
            v = (k < 128) ? 0.0f : W_hh[(2 * HDIM + h) * HDIM + (k - 128)];
        }
        __nv_bfloat16 hi = __float2bfloat16(v);
        __nv_bfloat16 lo = __float2bfloat16(v - __bfloat162float(hi));
        int kstep = k >> 4, kk = k & 15;
        int reg = kk >> 3, tg2 = (kk & 7) >> 1, half = kk & 1;
        int ntg = q >> 3, n = q & 7;
        int lane = n * 4 + tg2;
        size_t base = (size_t)(chunk * 32 + kstep) * 2048;
        size_t uhi = base + ntg * 128 + lane * 4 + reg;
        Wf16[uhi * 2 + half]       = hi;
        Wf16[(uhi + 2) * 2 + half] = lo;
    }
    if (idx < HDIM * D1) {
        int k = idx >> 6, j = idx & 63;
        float v = Wd1[j * HDIM + k];
        __nv_bfloat16 hi = __float2bfloat16(v);
        __nv_bfloat16 lo = __float2bfloat16(v - __bfloat162float(hi));
        int kstep = k >> 4, kk = k & 15;
        int reg = kk >> 3, tg2 = (kk & 7) >> 1, half = kk & 1;
        int ntg = j >> 3, n = j & 7;
        int lane = n * 4 + tg2;
        size_t uhi = (size_t)kstep * 1024 + ntg * 128 + lane * 4 + reg;
        Wd1f16[uhi * 2 + half]       = hi;
        Wd1f16[(uhi + 2) * 2 + half] = lo;
    }
    if (idx < NCOLS) {
        int c = idx >> 7, q = idx & 127, i = q >> 2, g = q & 3;
        int h = c * 32 + i;
        float bv;
        if (g == 3) bv = b_hh[2 * HDIM + h];
        else        bv = b_ih[g * HDIM + h] + b_hh[g * HDIM + h];
        g_bias[idx] = bv;
    }
}

// ----------------------------------------------------------------------------
// Persistent per-tile decoder. B operands stream from L2 via LDG.128 in
// fragment order with a distance-2 double-buffered register pipeline; no
// mainloop barriers. 2 groups of 8 warps on 2 chunks; mw = gwarp&1,
// nw = gwarp>>1.
// ----------------------------------------------------------------------------
__global__ void __launch_bounds__(NTH, 1)
decoder_kernel(const float* __restrict__ init_hidden,
               const float* __restrict__ plan,
               const float* __restrict__ gate,
               const float* __restrict__ init_state,
               const float* __restrict__ Wp, const float* __restrict__ bp,
               const float* __restrict__ Ws, const float* __restrict__ bs,
               const float* __restrict__ Wd2, const float* __restrict__ bd2,
               const float* __restrict__ bd1,
               float* __restrict__ out)
{
    extern __shared__ uint32_t sm32[];
    uint32_t* A_f  = sm32;                         // 32768 u32 (128KB)
    float* d1s    = (float*)(A_f + A_U32);         // 64*65 = 4160
    float* bias_s = d1s + BT * D1PAD;              // 1536
    float* xcoef  = bias_s + NCOLS;                // 1024
    float* bd1_s  = xcoef + 1024;                  // 64
    float* wd2_s  = bd1_s + D1;                    // 192
    float* bd2_s  = wd2_s + 192;                   // 4
    float* plan_s = bd2_s + 4;                     // 192
    float* st_s   = plan_s + BT * 3;               // 192
    float* gate_s = st_s + BT * 3;                 // 64
    float* red    = (float*)A_f;                   // decode reduction: x-kstep area (dead)

    const int tid   = threadIdx.x;
    const int lane  = tid & 31;
    const int warp  = tid >> 5;
    const int group = warp >> 3;     // 0 or 1
    const int gwarp = warp & 7;      // warp within group
    const int gid   = lane >> 2;     // 0..7
    const int tg    = lane & 3;      // 0..3
    const int mw    = gwarp & 1;     // 32-row half
    const int nw    = gwarp >> 1;    // 32-col quarter of 128-chunk
    const int bg0   = blockIdx.x * BT;
    const uint32_t woff  = (uint32_t)(nw * 512 + lane * 4);   // main B warp offset
    const uint32_t dwoff = (uint32_t)(nw * 256 + lane * 4);   // decode B warp offset

    // B stream address for linear kstep index j in this group's 6-chunk stream
    auto baddr = [&](int j) -> const uint32_t* {
        return g_Wf + (size_t)(2 * (j >> 5) + group) * CHUNK_U32
                    + (size_t)(j & 31) * 2048 + woff;
    };

    // ---- stage constants ----
    for (int i = tid; i < NCOLS; i += NTH) bias_s[i] = g_bias[i];
    if (tid < 128) {
        xcoef[tid * 8 + 0] = Ws[tid * 3 + 0];
        xcoef[tid * 8 + 1] = Ws[tid * 3 + 1];
        xcoef[tid * 8 + 2] = Ws[tid * 3 + 2];
        xcoef[tid * 8 + 3] = bs[tid];
        xcoef[tid * 8 + 4] = Wp[tid * 3 + 0];
        xcoef[tid * 8 + 5] = Wp[tid * 3 + 1];
        xcoef[tid * 8 + 6] = Wp[tid * 3 + 2];
        xcoef[tid * 8 + 7] = bp[tid];
    }
    if (tid < D1)  bd1_s[tid] = bd1[tid];
    if (tid < 192) wd2_s[tid] = Wd2[tid];
    if (tid < 3)   bd2_s[tid] = bd2[tid];
    if (tid < BT * 3) st_s[tid] = init_state[bg0 * 3 + tid];
    if (tid < BT)     gate_s[tid] = gate[bg0 + tid];

    // ---- init hidden: fp32 -> g_hidden and frag hi/lo -> A smem ----
    {
        const float4* src = (const float4*)(init_hidden + (size_t)bg0 * HDIM);
        float4* gh = (float4*)(g_hidden + (size_t)bg0 * HDIM);
        for (int i = tid; i < BT * HDIM / 4; i += NTH) {
            float4 v = src[i];
            gh[i] = v;
            int r = i / (HDIM / 4);
            int h4 = (i - r * (HDIM / 4)) * 4;
            a_write_pair(A_f, r, 128 + h4,     v.x, v.y);
            a_write_pair(A_f, r, 128 + h4 + 2, v.z, v.w);
        }
    }
    __syncthreads();

    // x-producer mapping: 512 threads -> (row b, 16-col group)
    const int xb  = tid & 63;
    const int xcg = (tid >> 6) * 16;

    for (int t = 0; t < T_STEPS; ++t) {
        // ---- stage plan_t ----
        if (tid < BT * 3) {
            int b = tid / 3, j = tid - b * 3;
            plan_s[tid] = plan[(size_t)(bg0 + b) * (T_STEPS * 3) + t * 3 + j];
        }
        __syncthreads();

        // ---- x = state@Ws^T + bs + gate*(plan@Wp^T + bp), frag hi/lo ----
        {
            float s0 = st_s[xb * 3], s1 = st_s[xb * 3 + 1], s2 = st_s[xb * 3 + 2];
            float p0 = plan_s[xb * 3], p1 = plan_s[xb * 3 + 1], p2 = plan_s[xb * 3 + 2];
            float gt = gate_s[xb];
            #pragma unroll 4
            for (int jj = 0; jj < 16; jj += 2) {
                const float* c0 = xcoef + (xcg + jj) * 8;
                const float* c1 = c0 + 8;
                float v0 = fmaf(c0[0], s0, fmaf(c0[1], s1, fmaf(c0[2], s2, c0[3])))
                         + gt * fmaf(c0[4], p0, fmaf(c0[5], p1, fmaf(c0[6], p2, c0[7])));
                float v1 = fmaf(c1[0], s0, fmaf(c1[1], s1, fmaf(c1[2], s2, c1[3])))
                         + gt * fmaf(c1[4], p0, fmaf(c1[5], p1, fmaf(c1[6], p2, c1[7])));
                a_write_pair(A_f, xb, xcg + jj, v0, v1);
            }
        }
        __syncthreads();

        // ======= main GEMM: 2 groups, group g owns chunks 2*cp+g; B via LDG =======
        // Double-buffered B registers, prefetch distance 2 ksteps.
        uint4 b0[4], b1[4];
        {
            const uint32_t* p0 = baddr(0);
            const uint32_t* p1 = baddr(1);
            #pragma unroll
            for (int nt = 0; nt < 4; ++nt) b0[nt] = __ldg((const uint4*)(p0 + nt * 128));
            #pragma unroll
            for (int nt = 0; nt < 4; ++nt) b1[nt] = __ldg((const uint4*)(p1 + nt * 128));
        }

        for (int cp = 0; cp < 6; ++cp) {
            const int c = 2 * cp + group;
            float acc[2][4][4];
            #pragma unroll
            for (int mt = 0; mt < 2; ++mt)
            #pragma unroll
            for (int nt = 0; nt < 4; ++nt) {
                int col = c * 128 + nw * 32 + nt * 8 + 2 * tg;
                float b0v = bias_s[col], b1v = bias_s[col + 1];
                acc[mt][nt][0] = b0v; acc[mt][nt][1] = b1v;
                acc[mt][nt][2] = b0v; acc[mt][nt][3] = b1v;
            }
            // prefetch oldh for this chunk's epilogue
            float oldv[2][4][2];
            if ((tg & 1) == 0) {
                #pragma unroll
                for (int mt = 0; mt < 2; ++mt)
                #pragma unroll
                for (int nt = 0; nt < 4; ++nt) {
                    int h = c * 32 + nw * 8 + nt * 2 + (tg >> 1);
                    size_t gr = (size_t)(bg0 + mw * 32 + mt * 16 + gid) * HDIM + h;
                    oldv[mt][nt][0] = g_hidden[gr];
                    oldv[mt][nt][1] = g_hidden[gr + (size_t)8 * HDIM];
                }
            }

            for (int kstep = 0; kstep < 32; kstep += 2) {
                // ---- even sub-iter: compute with b0, then refill b0 <- j+2 ----
                {
                    uint4 ah[2], al[2];
                    #pragma unroll
                    for (int mt = 0; mt < 2; ++mt) {
                        const uint32_t* ab = A_f + kstep * 1024 + (mw * 2 + mt) * 256 + lane * 4;
                        ah[mt] = *(const uint4*)ab;
                        al[mt] = *(const uint4*)(ab + 128);
                    }
                    #pragma unroll
                    for (int mt = 0; mt < 2; ++mt)
                    #pragma unroll
                    for (int nt = 0; nt < 4; ++nt)
                        mma16816(acc[mt][nt], ah[mt].x, ah[mt].y, ah[mt].z, ah[mt].w,
                                 b0[nt].x, b0[nt].y);
                    #pragma unroll
                    for (int mt = 0; mt < 2; ++mt)
                    #pragma unroll
                    for (int nt = 0; nt < 4; ++nt)
                        mma16816(acc[mt][nt], ah[mt].x, ah[mt].y, ah[mt].z, ah[mt].w,
                                 b0[nt].z, b0[nt].w);
                    #pragma unroll
                    for (int mt = 0; mt < 2; ++mt)
                    #pragma unroll
                    for (int nt = 0; nt < 4; ++nt)
                        mma16816(acc[mt][nt], al[mt].x, al[mt].y, al[mt].z, al[mt].w,
                                 b0[nt].x, b0[nt].y);
                    int j = cp * 32 + kstep + 2;
                    if (j < 192) {
                        const uint32_t* p = baddr(j);
                        #pragma unroll
                        for (int nt = 0; nt < 4; ++nt)
                            b0[nt] = __ldg((const uint4*)(p + nt * 128));
                    }
                }
                // ---- odd sub-iter: compute with b1, then refill b1 <- j+3 ----
                {
                    uint4 ah[2], al[2];
                    #pragma unroll
                    for (int mt = 0; mt < 2; ++mt) {
                        const uint32_t* ab = A_f + (kstep + 1) * 1024 + (mw * 2 + mt) * 256 + lane * 4;
                        ah[mt] = *(const uint4*)ab;
                        al[mt] = *(const uint4*)(ab + 128);
                    }
                    #pragma unroll
                    for (int mt = 0; mt < 2; ++mt)
                    #pragma unroll
                    for (int nt = 0; nt < 4; ++nt)
                        mma16816(acc[mt][nt], ah[mt].x, ah[mt].y, ah[mt].z, ah[mt].w,
                                 b1[nt].x, b1[nt].y);
                    #pragma unroll
                    for (int mt = 0; mt < 2; ++mt)
                    #pragma unroll
                    for (int nt = 0; nt < 4; ++nt)
                        mma16816(acc[mt][nt], ah[mt].x, ah[mt].y, ah[mt].z, ah[mt].w,
                                 b1[nt].z, b1[nt].w);
                    #pragma unroll
                    for (int mt = 0; mt < 2; ++mt)
                    #pragma unroll
                    for (int nt = 0; nt < 4; ++nt)
                        mma16816(acc[mt][nt], al[mt].x, al[mt].y, al[mt].z, al[mt].w,
                                 b1[nt].x, b1[nt].y);
                    int j = cp * 32 + kstep + 3;
                    if (j < 192) {
                        const uint32_t* p = baddr(j);
                        #pragma unroll
                        for (int nt = 0; nt < 4; ++nt)
                            b1[nt] = __ldg((const uint4*)(p + nt * 128));
                    }
                }
            }

            // ---- GRU pointwise (group-local; h ranges disjoint across groups) ----
            #pragma unroll
            for (int mt = 0; mt < 2; ++mt)
            #pragma unroll
            for (int nt = 0; nt < 4; ++nt) {
                float p0 = __shfl_xor_sync(0xffffffffu, acc[mt][nt][0], 1);
                float p1 = __shfl_xor_sync(0xffffffffu, acc[mt][nt][1], 1);
                float p2 = __shfl_xor_sync(0xffffffffu, acc[mt][nt][2], 1);
                float p3 = __shfl_xor_sync(0xffffffffu, acc[mt][nt][3], 1);
                if ((tg & 1) == 0) {
                    int h = c * 32 + nw * 8 + nt * 2 + (tg >> 1);
                    size_t gr = (size_t)(bg0 + mw * 32 + mt * 16 + gid) * HDIM + h;
                    float rg = sigmoid_f(acc[mt][nt][0]);
                    float zg = sigmoid_f(acc[mt][nt][1]);
                    float ng = tanh_f(p0 + (rg - 1.0f) * p1);   // s + (r-1)*hn
                    g_hidden[gr] = (1.0f - zg) * ng + zg * oldv[mt][nt][0];
                    float rg2 = sigmoid_f(acc[mt][nt][2]);
                    float zg2 = sigmoid_f(acc[mt][nt][3]);
                    float ng2 = tanh_f(p2 + (rg2 - 1.0f) * p3);
                    g_hidden[gr + (size_t)8 * HDIM] =
                        (1.0f - zg2) * ng2 + zg2 * oldv[mt][nt][1];
                }
            }
        }
        __syncthreads();   // all pointwise g_hidden writes done (both groups)

        // ---- refresh A smem hidden frags (hi/lo) from fp32 g_hidden ----
        {
            const float4* gh = (const float4*)(g_hidden + (size_t)bg0 * HDIM);
            for (int i = tid; i < BT * HDIM / 4; i += NTH) {
                float4 v = gh[i];
                int r = i / (HDIM / 4);
                int h4 = (i - r * (HDIM / 4)) * 4;
                a_write_pair(A_f, r, 128 + h4,     v.x, v.y);
                a_write_pair(A_f, r, 128 + h4 + 2, v.z, v.w);
            }
        }
        __syncthreads();

        // ======= decode GEMM: K split across groups; B via LDG =======
        float accd[2][2][4];
        {
            uint4 dbn[2];
            {
                const uint32_t* p = g_Wd1f + (size_t)(group * 12) * 1024 + dwoff;
                #pragma unroll
                for (int nt = 0; nt < 2; ++nt)
                    dbn[nt] = __ldg((const uint4*)(p + nt * 128));
            }
            #pragma unroll
            for (int mt = 0; mt < 2; ++mt)
            #pragma unroll
            for (int nt = 0; nt < 2; ++nt) {
                float b0v = 0.0f, b1v = 0.0f;
                if (group == 0) {
                    int col = nw * 16 + nt * 8 + 2 * tg;
                    b0v = bd1_s[col]; b1v = bd1_s[col + 1];
                }
                accd[mt][nt][0] = b0v; accd[mt][nt][1] = b1v;
                accd[mt][nt][2] = b0v; accd[mt][nt][3] = b1v;
            }
            for (int d = 0; d < 12; ++d) {
                uint4 dbc[2] = {dbn[0], dbn[1]};
                if (d < 11) {
                    const uint32_t* p = g_Wd1f + (size_t)(group * 12 + d + 1) * 1024 + dwoff;
                    #pragma unroll
                    for (int nt = 0; nt < 2; ++nt)
                        dbn[nt] = __ldg((const uint4*)(p + nt * 128));
                }
                int kstep = 8 + group * 12 + d;   // hidden region of A
                uint4 ah[2], al[2];
                #pragma unroll
                for (int mt = 0; mt < 2; ++mt) {
                    const uint32_t* ab = A_f + kstep * 1024 + (mw * 2 + mt) * 256 + lane * 4;
                    ah[mt] = *(const uint4*)ab;
                    al[mt] = *(const uint4*)(ab + 128);
                }
                #pragma unroll
                for (int mt = 0; mt < 2; ++mt)
                #pragma unroll
                for (int nt = 0; nt < 2; ++nt)
                    mma16816(accd[mt][nt], ah[mt].x, ah[mt].y, ah[mt].z, ah[mt].w,
                             dbc[nt].x, dbc[nt].y);
                #pragma unroll
                for (int mt = 0; mt < 2; ++mt)
                #pragma unroll
                for (int nt = 0; nt < 2; ++nt)
                    mma16816(accd[mt][nt], ah[mt].x, ah[mt].y, ah[mt].z, ah[mt].w,
                             dbc[nt].z, dbc[nt].w);
                #pragma unroll
                for (int mt = 0; mt < 2; ++mt)
                #pragma unroll
                for (int nt = 0; nt < 2; ++nt)
                    mma16816(accd[mt][nt], al[mt].x, al[mt].y, al[mt].z, al[mt].w,
                             dbc[nt].x, dbc[nt].y);
            }
        }
        __syncthreads();   // both groups done: A x-region (red) now dead, safe to write

        if (group == 1) {  // stage partial sums
            int base = (gwarp * 32 + lane) * 16;
            #pragma unroll
            for (int mt = 0; mt < 2; ++mt)
            #pragma unroll
            for (int nt = 0; nt < 2; ++nt) {
                int o = base + (mt * 2 + nt) * 4;
                red[o]     = accd[mt][nt][0];
                red[o + 1] = accd[mt][nt][1];
                red[o + 2] = accd[mt][nt][2];
                red[o + 3] = accd[mt][nt][3];
            }
        }
        __syncthreads();

        if (group == 0) {  // reduce + ELU -> d1s
            int base = (gwarp * 32 + lane) * 16;
            #pragma unroll
            for (int mt = 0; mt < 2; ++mt)
            #pragma unroll
            for (int nt = 0; nt < 2; ++nt) {
                int o = base + (mt * 2 + nt) * 4;
                float v0 = accd[mt][nt][0] + red[o];
                float v1 = accd[mt][nt][1] + red[o + 1];
                float v2 = accd[mt][nt][2] + red[o + 2];
                float v3 = accd[mt][nt][3] + red[o + 3];
                int col = nw * 16 + nt * 8 + 2 * tg;
                int row = mw * 32 + mt * 16 + gid;
                d1s[row * D1PAD + col]           = elu_f(v0);
                d1s[row * D1PAD + col + 1]       = elu_f(v1);
                d1s[(row + 8) * D1PAD + col]     = elu_f(v2);
                d1s[(row + 8) * D1PAD + col + 1] = elu_f(v3);
            }
        }
        __syncthreads();

        // ---- decode layer 2 + state update + output ----
        if (tid < BT * 3) {
            int b = tid / 3, j = tid - b * 3;
            const float* w = wd2_s + j * 64;
            const float* d = d1s + b * D1PAD;
            float sum = bd2_s[j];
            #pragma unroll
            for (int k = 0; k < 64; ++k)
                sum = fmaf(d[k], w[k], sum);
            float ns = st_s[tid] + sum;
            st_s[tid] = ns;
            out[(size_t)(bg0 + b) * (T_STEPS * 3) + t * 3 + j] = ns;
        }
        __syncthreads();
    }
}

// ----------------------------------------------------------------------------
extern "C" void kernel_launch(void* const* d_in, const int* in_sizes, int n_in,
                              void* d_out, int out_size)
{
    (void)in_sizes; (void)n_in; (void)out_size;
    const float* init_hidden = (const float*)d_in[0];
    const float* plan        = (const float*)d_in[1];
    const float* gate        = (const float*)d_in[2];
    const float* init_state  = (const float*)d_in[3];
    const float* Wp   = (const float*)d_in[4];
    const float* bp   = (const float*)d_in[5];
    const float* Ws   = (const float*)d_in[6];
    const float* bs   = (const float*)d_in[7];
    const float* W_ih = (const float*)d_in[8];
    const float* b_ih = (const float*)d_in[9];
    const float* W_hh = (const float*)d_in[10];
    const float* b_hh = (const float*)d_in[11];
    const float* Wd1  = (const float*)d_in[12];
    const float* bd1  = (const float*)d_in[13];
    const float* Wd2  = (const float*)d_in[14];
    const float* bd2  = (const float*)d_in[15];
    float* out = (float*)d_out;

    pack_kernel<<<(KTOT * NCOLS + 255) / 256, 256>>>(W_ih, W_hh, b_ih, b_hh, Wd1);

    const int smem_bytes = (A_U32 + BT * D1PAD + NCOLS + 1024
                            + D1 + 192 + 4 + BT * 3 + BT * 3 + BT) * 4;
    cudaFuncSetAttribute(decoder_kernel,
                         cudaFuncAttributeMaxDynamicSharedMemorySize, smem_bytes);
    decoder_kernel<<<B_TOTAL / BT, NTH, smem_bytes>>>(
        init_hidden, plan, gate, init_state,
        Wp, bp, Ws, bs, Wd2, bd2, bd1, out);
}

// round 14
// speedup vs baseline: 1.0722x; 1.0135x over previous
#include <cuda_runtime.h>
#include <cuda_bf16.h>
#include <cstdint>
#include <cstddef>

// ---------------- problem constants ----------------
#define B_TOTAL 32768
#define T_STEPS 30
#define HDIM    384
#define BT      64          // batch rows per CTA
#define NTH     512         // 16 warps = 2 groups of 8
#define KTOT    512         // [x(128) | hidden(384)]
#define NCOLS   1536        // 384 h * 4 gates (r,z,s,hn), gate-interleaved
#define NCHUNK  12          // 128 cols per chunk
#define SLAB_U32 4096       // one slab = 2 ksteps(32 k) x 128 cols, hi+lo fused
#define MAIN_SLABS 192      // 12 chunks * 16 slabs
#define DEC_SLABS  12
#define DSLAB_U32  2048
#define D1      64
#define D1PAD   65
#define A_U32   32768       // 32 ksteps * 1024 u32 (frag-ordered, hi+lo)
#define CHUNK_U32 65536     // 16 slabs * 4096 u32 per 128-col chunk

// ---------------- device scratch (no allocations allowed) ----------------
__device__ uint32_t g_Wf[(size_t)MAIN_SLABS * SLAB_U32];   // 3 MB main-W frags
__device__ uint32_t g_Wd1f[DEC_SLABS * DSLAB_U32];         // 96 KB Wd1 frags
__device__ float    g_bias[NCOLS];
__device__ float    g_hidden[(size_t)B_TOTAL * HDIM];      // fp32 recurrent state

// ---------------- helpers ----------------
__device__ __forceinline__ float sigmoid_f(float x) { return 1.0f / (1.0f + __expf(-x)); }
__device__ __forceinline__ float tanh_f(float x) {
    float e2 = __expf(2.0f * x);
    return 1.0f - 2.0f / (e2 + 1.0f);
}
__device__ __forceinline__ float elu_f(float x) {
    return x > 0.0f ? x : (__expf(x) - 1.0f);
}
__device__ __forceinline__ void mma16816(float* c,
    uint32_t a0, uint32_t a1, uint32_t a2, uint32_t a3, uint32_t b0, uint32_t b1)
{
    asm volatile(
        "mma.sync.aligned.m16n8k16.row.col.f32.bf16.bf16.f32 "
        "{%0,%1,%2,%3}, {%4,%5,%6,%7}, {%8,%9}, {%0,%1,%2,%3};\n"
        : "+f"(c[0]), "+f"(c[1]), "+f"(c[2]), "+f"(c[3])
        : "r"(a0), "r"(a1), "r"(a2), "r"(a3), "r"(b0), "r"(b1));
}

// Write element pair (row, k even, k+1) into frag-ordered A smem (hi + lo).
// A layout (u32): kstep*1024 + mt*256 + [hi:0 | lo:128] + lane*4 + reg
__device__ __forceinline__ void a_write_pair(uint32_t* A, int row, int k,
                                             float v0, float v1)
{
    int kstep = k >> 4, kk = k & 15;
    int mt = row >> 4, r16 = row & 15;
    int gid = r16 & 7, hi8 = r16 >> 3;
    int tg2 = (kk & 7) >> 1, k8 = kk >> 3;
    int reg = hi8 + 2 * k8;
    int lane = gid * 4 + tg2;
    uint32_t uidx = kstep * 1024 + mt * 256 + lane * 4 + reg;
    __nv_bfloat16 h0 = __float2bfloat16(v0);
    __nv_bfloat16 h1 = __float2bfloat16(v1);
    unsigned hw = (unsigned)__bfloat16_as_ushort(h0)
                | ((unsigned)__bfloat16_as_ushort(h1) << 16);
    unsigned lw = (unsigned)__bfloat16_as_ushort(__float2bfloat16(v0 - __bfloat162float(h0)))
                | ((unsigned)__bfloat16_as_ushort(__float2bfloat16(v1 - __bfloat162float(h1))) << 16);
    A[uidx]       = hw;
    A[uidx + 128] = lw;
}

// ----------------------------------------------------------------------------
// Pack: W = [W_ih | W_hh] -> bf16 hi/lo, fused-fragment order (unchanged).
// ----------------------------------------------------------------------------
__global__ void pack_kernel(const float* __restrict__ W_ih,
                            const float* __restrict__ W_hh,
                            const float* __restrict__ b_ih,
                            const float* __restrict__ b_hh,
                            const float* __restrict__ Wd1)
{
    int idx = blockIdx.x * blockDim.x + threadIdx.x;
    __nv_bfloat16* Wf16   = (__nv_bfloat16*)g_Wf;
    __nv_bfloat16* Wd1f16 = (__nv_bfloat16*)g_Wd1f;

    if (idx < KTOT * NCOLS) {
        int k = idx / NCOLS;
        int col = idx - k * NCOLS;
        int chunk = col >> 7, q = col & 127;
        int i = q >> 2, g = q & 3, h = chunk * 32 + i;
        float v;
        if (g < 3) {
            int row = g * HDIM + h;
            v = (k < 128) ? W_ih[row * 128 + k] : W_hh[row * HDIM + (k - 128)];
        } else {
            v = (k < 128) ? 0.0f : W_hh[(2 * HDIM + h) * HDIM + (k - 128)];
        }
        __nv_bfloat16 hi = __float2bfloat16(v);
        __nv_bfloat16 lo = __float2bfloat16(v - __bfloat162float(hi));
        int kstep = k >> 4, kk = k & 15;
        int reg = kk >> 3, tg2 = (kk & 7) >> 1, half = kk & 1;
        int ntg = q >> 3, n = q & 7;
        int lane = n * 4 + tg2;
        size_t base = (size_t)(chunk * 32 + kstep) * 2048;
        size_t uhi = base + ntg * 128 + lane * 4 + reg;
        Wf16[uhi * 2 + half]       = hi;
        Wf16[(uhi + 2) * 2 + half] = lo;
    }
    if (idx < HDIM * D1) {
        int k = idx >> 6, j = idx & 63;
        float v = Wd1[j * HDIM + k];
        __nv_bfloat16 hi = __float2bfloat16(v);
        __nv_bfloat16 lo = __float2bfloat16(v - __bfloat162float(hi));
        int kstep = k >> 4, kk = k & 15;
        int reg = kk >> 3, tg2 = (kk & 7) >> 1, half = kk & 1;
        int ntg = j >> 3, n = j & 7;
        int lane = n * 4 + tg2;
        size_t uhi = (size_t)kstep * 1024 + ntg * 128 + lane * 4 + reg;
        Wd1f16[uhi * 2 + half]       = hi;
        Wd1f16[(uhi + 2) * 2 + half] = lo;
    }
    if (idx < NCOLS) {
        int c = idx >> 7, q = idx & 127, i = q >> 2, g = q & 3;
        int h = c * 32 + i;
        float bv;
        if (g == 3) bv = b_hh[2 * HDIM + h];
        else        bv = b_ih[g * HDIM + h] + b_hh[g * HDIM + h];
        g_bias[idx] = bv;
    }
}

// ----------------------------------------------------------------------------
// Persistent per-tile decoder. Main GEMM tiling (4 mt, 2 nt): each warp owns
// all 64 rows x 16 unique cols -> B LDG traffic is 1x unique (no mw-pair
// duplication at L2). B streams via LDG.128 fragment-order, double-buffered
// at distance 2; no mainloop barriers. 2 groups of 8 warps on 2 chunks.
// ----------------------------------------------------------------------------
__global__ void __launch_bounds__(NTH, 1)
decoder_kernel(const float* __restrict__ init_hidden,
               const float* __restrict__ plan,
               const float* __restrict__ gate,
               const float* __restrict__ init_state,
               const float* __restrict__ Wp, const float* __restrict__ bp,
               const float* __restrict__ Ws, const float* __restrict__ bs,
               const float* __restrict__ Wd2, const float* __restrict__ bd2,
               const float* __restrict__ bd1,
               float* __restrict__ out)
{
    extern __shared__ uint32_t sm32[];
    uint32_t* A_f  = sm32;                         // 32768 u32 (128KB)
    float* d1s    = (float*)(A_f + A_U32);         // 64*65 = 4160
    float* bias_s = d1s + BT * D1PAD;              // 1536
    float* xcoef  = bias_s + NCOLS;                // 1024
    float* bd1_s  = xcoef + 1024;                  // 64
    float* wd2_s  = bd1_s + D1;                    // 192
    float* bd2_s  = wd2_s + 192;                   // 4
    float* plan_s = bd2_s + 4;                     // 192
    float* st_s   = plan_s + BT * 3;               // 192
    float* gate_s = st_s + BT * 3;                 // 64
    float* red    = (float*)A_f;                   // decode reduction: x-kstep area (dead)

    const int tid   = threadIdx.x;
    const int lane  = tid & 31;
    const int warp  = tid >> 5;
    const int group = warp >> 3;     // 0 or 1
    const int gwarp = warp & 7;      // warp within group
    const int gid   = lane >> 2;     // 0..7
    const int tg    = lane & 3;      // 0..3
    const int nw8   = gwarp;         // main GEMM: warp's unique 16-col slice
    const int dmw   = gwarp & 1;     // decode GEMM mapping (unchanged)
    const int dnw   = gwarp >> 1;
    const int bg0   = blockIdx.x * BT;
    const uint32_t woff  = (uint32_t)(nw8 * 256 + lane * 4);  // main B warp offset
    const uint32_t dwoff = (uint32_t)(dnw * 256 + lane * 4);  // decode B warp offset

    // B stream address for linear kstep index j in this group's 6-chunk stream
    auto baddr = [&](int j) -> const uint32_t* {
        return g_Wf + (size_t)(2 * (j >> 5) + group) * CHUNK_U32
                    + (size_t)(j & 31) * 2048 + woff;
    };

    // ---- stage constants ----
    for (int i = tid; i < NCOLS; i += NTH) bias_s[i] = g_bias[i];
    if (tid < 128) {
        xcoef[tid * 8 + 0] = Ws[tid * 3 + 0];
        xcoef[tid * 8 + 1] = Ws[tid * 3 + 1];
        xcoef[tid * 8 + 2] = Ws[tid * 3 + 2];
        xcoef[tid * 8 + 3] = bs[tid];
        xcoef[tid * 8 + 4] = Wp[tid * 3 + 0];
        xcoef[tid * 8 + 5] = Wp[tid * 3 + 1];
        xcoef[tid * 8 + 6] = Wp[tid * 3 + 2];
        xcoef[tid * 8 + 7] = bp[tid];
    }
    if (tid < D1)  bd1_s[tid] = bd1[tid];
    if (tid < 192) wd2_s[tid] = Wd2[tid];
    if (tid < 3)   bd2_s[tid] = bd2[tid];
    if (tid < BT * 3) st_s[tid] = init_state[bg0 * 3 + tid];
    if (tid < BT)     gate_s[tid] = gate[bg0 + tid];

    // ---- init hidden: fp32 -> g_hidden and frag hi/lo -> A smem ----
    {
        const float4* src = (const float4*)(init_hidden + (size_t)bg0 * HDIM);
        float4* gh = (float4*)(g_hidden + (size_t)bg0 * HDIM);
        for (int i = tid; i < BT * HDIM / 4; i += NTH) {
            float4 v = src[i];
            gh[i] = v;
            int r = i / (HDIM / 4);
            int h4 = (i - r * (HDIM / 4)) * 4;
            a_write_pair(A_f, r, 128 + h4,     v.x, v.y);
            a_write_pair(A_f, r, 128 + h4 + 2, v.z, v.w);
        }
    }
    __syncthreads();

    // x-producer mapping: 512 threads -> (row b, 16-col group)
    const int xb  = tid & 63;
    const int xcg = (tid >> 6) * 16;

    for (int t = 0; t < T_STEPS; ++t) {
        // ---- stage plan_t ----
        if (tid < BT * 3) {
            int b = tid / 3, j = tid - b * 3;
            plan_s[tid] = plan[(size_t)(bg0 + b) * (T_STEPS * 3) + t * 3 + j];
        }
        __syncthreads();

        // ---- x = state@Ws^T + bs + gate*(plan@Wp^T + bp), frag hi/lo ----
        {
            float s0 = st_s[xb * 3], s1 = st_s[xb * 3 + 1], s2 = st_s[xb * 3 + 2];
            float p0 = plan_s[xb * 3], p1 = plan_s[xb * 3 + 1], p2 = plan_s[xb * 3 + 2];
            float gt = gate_s[xb];
            #pragma unroll 4
            for (int jj = 0; jj < 16; jj += 2) {
                const float* c0 = xcoef + (xcg + jj) * 8;
                const float* c1 = c0 + 8;
                float v0 = fmaf(c0[0], s0, fmaf(c0[1], s1, fmaf(c0[2], s2, c0[3])))
                         + gt * fmaf(c0[4], p0, fmaf(c0[5], p1, fmaf(c0[6], p2, c0[7])));
                float v1 = fmaf(c1[0], s0, fmaf(c1[1], s1, fmaf(c1[2], s2, c1[3])))
                         + gt * fmaf(c1[4], p0, fmaf(c1[5], p1, fmaf(c1[6], p2, c1[7])));
                a_write_pair(A_f, xb, xcg + jj, v0, v1);
            }
        }
        __syncthreads();

        // ======= main GEMM: group g owns chunks 2*cp+g; warp = 64 rows x 16 cols =======
        uint4 b0[2], b1[2];   // double-buffered B, distance 2
        {
            const uint32_t* p0 = baddr(0);
            const uint32_t* p1 = baddr(1);
            #pragma unroll
            for (int nt = 0; nt < 2; ++nt) b0[nt] = __ldg((const uint4*)(p0 + nt * 128));
            #pragma unroll
            for (int nt = 0; nt < 2; ++nt) b1[nt] = __ldg((const uint4*)(p1 + nt * 128));
        }

        for (int cp = 0; cp < 6; ++cp) {
            const int c = 2 * cp + group;
            float acc[4][2][4];
            #pragma unroll
            for (int mt = 0; mt < 4; ++mt)
            #pragma unroll
            for (int nt = 0; nt < 2; ++nt) {
                int col = c * 128 + nw8 * 16 + nt * 8 + 2 * tg;
                float b0v = bias_s[col], b1v = bias_s[col + 1];
                acc[mt][nt][0] = b0v; acc[mt][nt][1] = b1v;
                acc[mt][nt][2] = b0v; acc[mt][nt][3] = b1v;
            }
            // prefetch oldh for this chunk's epilogue
            float oldv[4][2][2];
            if ((tg & 1) == 0) {
                #pragma unroll
                for (int mt = 0; mt < 4; ++mt)
                #pragma unroll
                for (int nt = 0; nt < 2; ++nt) {
                    int h = c * 32 + nw8 * 4 + nt * 2 + (tg >> 1);
                    size_t gr = (size_t)(bg0 + mt * 16 + gid) * HDIM + h;
                    oldv[mt][nt][0] = g_hidden[gr];
                    oldv[mt][nt][1] = g_hidden[gr + (size_t)8 * HDIM];
                }
            }

            for (int kstep = 0; kstep < 32; kstep += 2) {
                // ---- even sub-iter: compute with b0, refill b0 <- j+2 ----
                {
                    uint4 ah[4], al[4];
                    #pragma unroll
                    for (int mt = 0; mt < 4; ++mt) {
                        const uint32_t* ab = A_f + kstep * 1024 + mt * 256 + lane * 4;
                        ah[mt] = *(const uint4*)ab;
                        al[mt] = *(const uint4*)(ab + 128);
                    }
                    #pragma unroll
                    for (int mt = 0; mt < 4; ++mt)
                    #pragma unroll
                    for (int nt = 0; nt < 2; ++nt)
                        mma16816(acc[mt][nt], ah[mt].x, ah[mt].y, ah[mt].z, ah[mt].w,
                                 b0[nt].x, b0[nt].y);
                    #pragma unroll
                    for (int mt = 0; mt < 4; ++mt)
                    #pragma unroll
                    for (int nt = 0; nt < 2; ++nt)
                        mma16816(acc[mt][nt], ah[mt].x, ah[mt].y, ah[mt].z, ah[mt].w,
                                 b0[nt].z, b0[nt].w);
                    #pragma unroll
                    for (int mt = 0; mt < 4; ++mt)
                    #pragma unroll
                    for (int nt = 0; nt < 2; ++nt)
                        mma16816(acc[mt][nt], al[mt].x, al[mt].y, al[mt].z, al[mt].w,
                                 b0[nt].x, b0[nt].y);
                    int j = cp * 32 + kstep + 2;
                    if (j < 192) {
                        const uint32_t* p = baddr(j);
                        #pragma unroll
                        for (int nt = 0; nt < 2; ++nt)
                            b0[nt] = __ldg((const uint4*)(p + nt * 128));
                    }
                }
                // ---- odd sub-iter: compute with b1, refill b1 <- j+3 ----
                {
                    uint4 ah[4], al[4];
                    #pragma unroll
                    for (int mt = 0; mt < 4; ++mt) {
                        const uint32_t* ab = A_f + (kstep + 1) * 1024 + mt * 256 + lane * 4;
                        ah[mt] = *(const uint4*)ab;
                        al[mt] = *(const uint4*)(ab + 128);
                    }
                    #pragma unroll
                    for (int mt = 0; mt < 4; ++mt)
                    #pragma unroll
                    for (int nt = 0; nt < 2; ++nt)
                        mma16816(acc[mt][nt], ah[mt].x, ah[mt].y, ah[mt].z, ah[mt].w,
                                 b1[nt].x, b1[nt].y);
                    #pragma unroll
                    for (int mt = 0; mt < 4; ++mt)
                    #pragma unroll
                    for (int nt = 0; nt < 2; ++nt)
                        mma16816(acc[mt][nt], ah[mt].x, ah[mt].y, ah[mt].z, ah[mt].w,
                                 b1[nt].z, b1[nt].w);
                    #pragma unroll
                    for (int mt = 0; mt < 4; ++mt)
                    #pragma unroll
                    for (int nt = 0; nt < 2; ++nt)
                        mma16816(acc[mt][nt], al[mt].x, al[mt].y, al[mt].z, al[mt].w,
                                 b1[nt].x, b1[nt].y);
                    int j = cp * 32 + kstep + 3;
                    if (j < 192) {
                        const uint32_t* p = baddr(j);
                        #pragma unroll
                        for (int nt = 0; nt < 2; ++nt)
                            b1[nt] = __ldg((const uint4*)(p + nt * 128));
                    }
                }
            }

            // ---- GRU pointwise: even tg has (r,z), odd tg has (s,hn); xor-1 pair ----
            #pragma unroll
            for (int mt = 0; mt < 4; ++mt)
            #pragma unroll
            for (int nt = 0; nt < 2; ++nt) {
                float p0 = __shfl_xor_sync(0xffffffffu, acc[mt][nt][0], 1);
                float p1 = __shfl_xor_sync(0xffffffffu, acc[mt][nt][1], 1);
                float p2 = __shfl_xor_sync(0xffffffffu, acc[mt][nt][2], 1);
                float p3 = __shfl_xor_sync(0xffffffffu, acc[mt][nt][3], 1);
                if ((tg & 1) == 0) {
                    int h = c * 32 + nw8 * 4 + nt * 2 + (tg >> 1);
                    size_t gr = (size_t)(bg0 + mt * 16 + gid) * HDIM + h;
                    float rg = sigmoid_f(acc[mt][nt][0]);
                    float zg = sigmoid_f(acc[mt][nt][1]);
                    float ng = tanh_f(p0 + (rg - 1.0f) * p1);   // s + (r-1)*hn
                    g_hidden[gr] = (1.0f - zg) * ng + zg * oldv[mt][nt][0];
                    float rg2 = sigmoid_f(acc[mt][nt][2]);
                    float zg2 = sigmoid_f(acc[mt][nt][3]);
                    float ng2 = tanh_f(p2 + (rg2 - 1.0f) * p3);
                    g_hidden[gr + (size_t)8 * HDIM] =
                        (1.0f - zg2) * ng2 + zg2 * oldv[mt][nt][1];
                }
            }
        }
        __syncthreads();   // all pointwise g_hidden writes done (both groups)

        // ---- refresh A smem hidden frags (hi/lo) from fp32 g_hidden ----
        {
            const float4* gh = (const float4*)(g_hidden + (size_t)bg0 * HDIM);
            for (int i = tid; i < BT * HDIM / 4; i += NTH) {
                float4 v = gh[i];
                int r = i / (HDIM / 4);
                int h4 = (i - r * (HDIM / 4)) * 4;
                a_write_pair(A_f, r, 128 + h4,     v.x, v.y);
                a_write_pair(A_f, r, 128 + h4 + 2, v.z, v.w);
            }
        }
        __syncthreads();

        // ======= decode GEMM: K split across groups; B via LDG (mapping unchanged) =======
        float accd[2][2][4];
        {
            uint4 dbn[2];
            {
                const uint32_t* p = g_Wd1f + (size_t)(group * 12) * 1024 + dwoff;
                #pragma unroll
                for (int nt = 0; nt < 2; ++nt)
                    dbn[nt] = __ldg((const uint4*)(p + nt * 128));
            }
            #pragma unroll
            for (int mt = 0; mt < 2; ++mt)
            #pragma unroll
            for (int nt = 0; nt < 2; ++nt) {
                float b0v = 0.0f, b1v = 0.0f;
                if (group == 0) {
                    int col = dnw * 16 + nt * 8 + 2 * tg;
                    b0v = bd1_s[col]; b1v = bd1_s[col + 1];
                }
                accd[mt][nt][0] = b0v; accd[mt][nt][1] = b1v;
                accd[mt][nt][2] = b0v; accd[mt][nt][3] = b1v;
            }
            for (int d = 0; d < 12; ++d) {
                uint4 dbc[2] = {dbn[0], dbn[1]};
                if (d < 11) {
                    const uint32_t* p = g_Wd1f + (size_t)(group * 12 + d + 1) * 1024 + dwoff;
                    #pragma unroll
                    for (int nt = 0; nt < 2; ++nt)
                        dbn[nt] = __ldg((const uint4*)(p + nt * 128));
                }
                int kstep = 8 + group * 12 + d;   // hidden region of A
                uint4 ah[2], al[2];
                #pragma unroll
                for (int mt = 0; mt < 2; ++mt) {
                    const uint32_t* ab = A_f + kstep * 1024 + (dmw * 2 + mt) * 256 + lane * 4;
                    ah[mt] = *(const uint4*)ab;
                    al[mt] = *(const uint4*)(ab + 128);
                }
                #pragma unroll
                for (int mt = 0; mt < 2; ++mt)
                #pragma unroll
                for (int nt = 0; nt < 2; ++nt)
                    mma16816(accd[mt][nt], ah[mt].x, ah[mt].y, ah[mt].z, ah[mt].w,
                             dbc[nt].x, dbc[nt].y);
                #pragma unroll
                for (int mt = 0; mt < 2; ++mt)
                #pragma unroll
                for (int nt = 0; nt < 2; ++nt)
                    mma16816(accd[mt][nt], ah[mt].x, ah[mt].y, ah[mt].z, ah[mt].w,
                             dbc[nt].z, dbc[nt].w);
                #pragma unroll
                for (int mt = 0; mt < 2; ++mt)
                #pragma unroll
                for (int nt = 0; nt < 2; ++nt)
                    mma16816(accd[mt][nt], al[mt].x, al[mt].y, al[mt].z, al[mt].w,
                             dbc[nt].x, dbc[nt].y);
            }
        }
        __syncthreads();   // both groups done: A x-region (red) now dead, safe to write

        if (group == 1) {  // stage partial sums
            int base = (gwarp * 32 + lane) * 16;
            #pragma unroll
            for (int mt = 0; mt < 2; ++mt)
            #pragma unroll
            for (int nt = 0; nt < 2; ++nt) {
                int o = base + (mt * 2 + nt) * 4;
                red[o]     = accd[mt][nt][0];
                red[o + 1] = accd[mt][nt][1];
                red[o + 2] = accd[mt][nt][2];
                red[o + 3] = accd[mt][nt][3];
            }
        }
        __syncthreads();

        if (group == 0) {  // reduce + ELU -> d1s
            int base = (gwarp * 32 + lane) * 16;
            #pragma unroll
            for (int mt = 0; mt < 2; ++mt)
            #pragma unroll
            for (int nt = 0; nt < 2; ++nt) {
                int o = base + (mt * 2 + nt) * 4;
                float v0 = accd[mt][nt][0] + red[o];
                float v1 = accd[mt][nt][1] + red[o + 1];
                float v2 = accd[mt][nt][2] + red[o + 2];
                float v3 = accd[mt][nt][3] + red[o + 3];
                int col = dnw * 16 + nt * 8 + 2 * tg;
                int row = dmw * 32 + mt * 16 + gid;
                d1s[row * D1PAD + col]           = elu_f(v0);
                d1s[row * D1PAD + col + 1]       = elu_f(v1);
                d1s[(row + 8) * D1PAD + col]     = elu_f(v2);
                d1s[(row + 8) * D1PAD + col + 1] = elu_f(v3);
            }
        }
        __syncthreads();

        // ---- decode layer 2 + state update + output ----
        if (tid < BT * 3) {
            int b = tid / 3, j = tid - b * 3;
            const float* w = wd2_s + j * 64;
            const float* d = d1s + b * D1PAD;
            float sum = bd2_s[j];
            #pragma unroll
            for (int k = 0; k < 64; ++k)
                sum = fmaf(d[k], w[k], sum);
            float ns = st_s[tid] + sum;
            st_s[tid] = ns;
            out[(size_t)(bg0 + b) * (T_STEPS * 3) + t * 3 + j] = ns;
        }
        __syncthreads();
    }
}

// ----------------------------------------------------------------------------
extern "C" void kernel_launch(void* const* d_in, const int* in_sizes, int n_in,
                              void* d_out, int out_size)
{
    (void)in_sizes; (void)n_in; (void)out_size;
    const float* init_hidden = (const float*)d_in[0];
    const float* plan        = (const float*)d_in[1];
    const float* gate        = (const float*)d_in[2];
    const float* init_state  = (const float*)d_in[3];
    const float* Wp   = (const float*)d_in[4];
    const float* bp   = (const float*)d_in[5];
    const float* Ws   = (const float*)d_in[6];
    const float* bs   = (const float*)d_in[7];
    const float* W_ih = (const float*)d_in[8];
    const float* b_ih = (const float*)d_in[9];
    const float* W_hh = (const float*)d_in[10];
    const float* b_hh = (const float*)d_in[11];
    const float* Wd1  = (const float*)d_in[12];
    const float* bd1  = (const float*)d_in[13];
    const float* Wd2  = (const float*)d_in[14];
    const float* bd2  = (const float*)d_in[15];
    float* out = (float*)d_out;

    pack_kernel<<<(KTOT * NCOLS + 255) / 256, 256>>>(W_ih, W_hh, b_ih, b_hh, Wd1);

    const int smem_bytes = (A_U32 + BT * D1PAD + NCOLS + 1024
                            + D1 + 192 + 4 + BT * 3 + BT * 3 + BT) * 4;
    cudaFuncSetAttribute(decoder_kernel,
                         cudaFuncAttributeMaxDynamicSharedMemorySize, smem_bytes);
    decoder_kernel<<<B_TOTAL / BT, NTH, smem_bytes>>>(
        init_hidden, plan, gate, init_state,
        Wp, bp, Ws, bs, Wd2, bd2, bd1, out);
}